// round 16
// baseline (speedup 1.0000x reference)
#include <cuda_runtime.h>
#include <cuda_fp16.h>
#include <cstdint>

#define SEQ  1024
#define CC   768
#define NH   12
#define HD   64
#define MM   8192
#define NQKV 2304

__device__ __half g_x[MM*CC];
__device__ __half g_y[MM*CC];
__device__ __half g_w[NQKV*CC];
__device__ __half g_p[CC*CC];
__device__ __half g_q[MM*CC];                     // q * 0.125*log2(e)
__device__ __half g_k[MM*CC];
__device__ __half g_v[MM*CC];
__device__ __half g_ao[MM*CC];

#define LOG2E 1.4426950408889634f

// ---------------- helpers ----------------------------------------------------
__device__ __forceinline__ uint32_t smem_u32(const void* p) {
    uint32_t a;
    asm("{ .reg .u64 t; cvta.to.shared.u64 t, %1; cvt.u32.u64 %0, t; }" : "=r"(a) : "l"(p));
    return a;
}
__device__ __forceinline__ void cpa16(uint32_t s, const void* g) {
    asm volatile("cp.async.cg.shared.global [%0], [%1], 16;" :: "r"(s), "l"(g));
}
__device__ __forceinline__ void cpa_commit() { asm volatile("cp.async.commit_group;"); }
template<int N> __device__ __forceinline__ void cpa_wait() {
    asm volatile("cp.async.wait_group %0;" :: "n"(N));
}
__device__ __forceinline__ void ldsm4(uint32_t& r0, uint32_t& r1, uint32_t& r2, uint32_t& r3,
                                      uint32_t addr) {
    asm volatile("ldmatrix.sync.aligned.m8n8.x4.shared.b16 {%0,%1,%2,%3}, [%4];"
                 : "=r"(r0), "=r"(r1), "=r"(r2), "=r"(r3) : "r"(addr));
}
__device__ __forceinline__ void ldsm4t(uint32_t& r0, uint32_t& r1, uint32_t& r2, uint32_t& r3,
                                       uint32_t addr) {
    asm volatile("ldmatrix.sync.aligned.m8n8.x4.trans.shared.b16 {%0,%1,%2,%3}, [%4];"
                 : "=r"(r0), "=r"(r1), "=r"(r2), "=r"(r3) : "r"(addr));
}
__device__ __forceinline__ void mmaf16(float* c, const uint32_t* a, const uint32_t* b) {
    asm volatile("mma.sync.aligned.m16n8k16.row.col.f32.f16.f16.f32 "
                 "{%0,%1,%2,%3}, {%4,%5,%6,%7}, {%8,%9}, {%0,%1,%2,%3};"
                 : "+f"(c[0]), "+f"(c[1]), "+f"(c[2]), "+f"(c[3])
                 : "r"(a[0]), "r"(a[1]), "r"(a[2]), "r"(a[3]), "r"(b[0]), "r"(b[1]));
}
__device__ __forceinline__ uint32_t h2pack(float a, float b) {
    __half2 h = __floats2half2_rn(a, b);
    return *(uint32_t*)&h;
}
__device__ __forceinline__ uint32_t ex2h2(uint32_t in) {
    uint32_t r;
    asm("ex2.approx.f16x2 %0, %1;" : "=r"(r) : "r"(in));
    return r;
}
__device__ __forceinline__ float sigmoidf_(float x) { return 1.f/(1.f+__expf(-x)); }
__device__ __forceinline__ uint32_t swzb(int row, int cb) {
    return (uint32_t)(row*128 + ((((cb) >> 4) ^ (row & 7)) << 4));
}

// ---------------------------------------------------------------------------
__global__ void prep_all(const float* __restrict__ x, const float* __restrict__ qw,
                         const float* __restrict__ kvw, const float* __restrict__ pw) {
    const int NX = MM*CC, QW = CC*CC, KVW = 2*CC*CC, PW = CC*CC;
    const int T0 = NX, T1 = NX + QW, T2 = T1 + KVW, TOT = T2 + PW;
    for (int i = blockIdx.x*blockDim.x + threadIdx.x; i < TOT; i += gridDim.x*blockDim.x) {
        if (i < T0)      g_x[i] = __float2half_rn(x[i]);
        else if (i < T1) g_w[i - T0] = __float2half_rn(qw[i - T0]);
        else if (i < T2) g_w[i - T0] = __float2half_rn(kvw[i - T1]);
        else             g_p[i - T2] = __float2half_rn(pw[i - T2]);
    }
}

// ---------------------------------------------------------------------------
// Coalesced LN (unchanged from R15).
// ---------------------------------------------------------------------------
#define LNP 773

__global__ void ln_kernel(const float* __restrict__ y,
                          const float* __restrict__ gam, const float* __restrict__ bet) {
    extern __shared__ float sv[];
    __shared__ float sstat[32][2];
    int b = blockIdx.y, hw0 = blockIdx.x*32;
    const float* yb = y + (size_t)b*CC*SEQ + hw0;
    int t = threadIdx.x, w = t >> 5, lane = t & 31;

#pragma unroll 8
    for (int i = 0; i < 96; i++) {
        int li = t + i*256;
        int c = li >> 5, j = li & 31;
        sv[j*LNP + c] = yb[(size_t)c*SEQ + j];
    }
    __syncthreads();

#pragma unroll
    for (int rr = 0; rr < 4; rr++) {
        int r = w*4 + rr;
        float s = 0.f, s2 = 0.f;
#pragma unroll
        for (int c = lane; c < CC; c += 32) {
            float v = sv[r*LNP + c];
            s += v; s2 += v*v;
        }
#pragma unroll
        for (int o = 16; o > 0; o >>= 1) {
            s  += __shfl_xor_sync(0xffffffffu, s,  o);
            s2 += __shfl_xor_sync(0xffffffffu, s2, o);
        }
        if (lane == 0) {
            float mean = s*(1.f/CC), var = s2*(1.f/CC) - mean*mean;
            sstat[r][0] = mean;
            sstat[r][1] = rsqrtf(var + 1e-5f);
        }
    }
    __syncthreads();

#pragma unroll
    for (int rr = 0; rr < 4; rr++) {
        int r = w*4 + rr;
        float mean = sstat[r][0], rstd = sstat[r][1];
        size_t mrow = ((size_t)b*SEQ + hw0 + r)*CC;
#pragma unroll
        for (int c2 = lane; c2 < 384; c2 += 32) {
            int c = c2*2;
            float o0 = (sv[r*LNP + c]   - mean)*rstd*gam[c]   + bet[c];
            float o1 = (sv[r*LNP + c+1] - mean)*rstd*gam[c+1] + bet[c+1];
            *(__half2*)(g_y + mrow + c) = __floats2half2_rn(o0, o1);
        }
    }
}

// ---------------------------------------------------------------------------
// FUSED qkv GEMM + gating (unchanged from R15, 256 threads).
// ---------------------------------------------------------------------------
#define PITCH2 144
#define BUFX  18432
#define BUFW2 9216
#define QSTG  (2*BUFX + BUFW2)

__global__ __launch_bounds__(256, 2)
void qkv_fused(const float* __restrict__ qb, const float* __restrict__ kvb) {
    extern __shared__ __align__(16) char smraw[];
    uint32_t smb = smem_u32(smraw);
    int t = threadIdx.x, lane = t & 31, w = t >> 5;
    int wm = w >> 1, wn = w & 1;
    int bx = blockIdx.x;
    int m0 = blockIdx.y * 128;
    int j0 = bx * 64;

    const __half* sx = g_x + (size_t)m0*CC;
    const __half* sy = g_y + (size_t)m0*CC;
    const __half* sw = g_w + (size_t)j0*CC;

    auto load_stage = [&](int s, int k0) {
        uint32_t base = smb + (s & 1)*QSTG;
#pragma unroll
        for (int i = 0; i < 4; i++) {
            int c = t + i*256;
            int row = c >> 3, ch = c & 7;
            cpa16(base + row*PITCH2 + ch*16,          sx + (size_t)row*CC + k0 + ch*8);
            cpa16(base + BUFX + row*PITCH2 + ch*16,   sy + (size_t)row*CC + k0 + ch*8);
        }
#pragma unroll
        for (int i = 0; i < 2; i++) {
            int c = t + i*256;
            int row = c >> 3, ch = c & 7;
            cpa16(base + 2*BUFX + row*PITCH2 + ch*16, sw + (size_t)row*CC + k0 + ch*8);
        }
        cpa_commit();
    };

    float accx[2][4][4], accy[2][4][4];
#pragma unroll
    for (int mi = 0; mi < 2; mi++)
#pragma unroll
        for (int ni = 0; ni < 4; ni++)
#pragma unroll
            for (int e = 0; e < 4; e++) { accx[mi][ni][e] = 0.f; accy[mi][ni][e] = 0.f; }

    load_stage(0, 0);

    const int NSTG = CC/64;
    int a_row  = wm*32 + (lane & 15);
    int a_coff = (lane >> 4) * 16;
    int b_row  = (lane & 7) + ((lane >> 1) & 8);
    int b_coff = (lane & 8) * 2;

#pragma unroll 1
    for (int s = 0; s < NSTG; s++) {
        cpa_wait<0>();
        __syncthreads();
        if (s + 1 < NSTG) load_stage(s + 1, (s + 1)*64);
        uint32_t bX = smb + (s & 1)*QSTG;
        uint32_t bY = bX + BUFX, bW = bX + 2*BUFX;
#pragma unroll
        for (int ks = 0; ks < 4; ks++) {
            int kb = ks*32;
            uint32_t xx[2][4], yy[2][4], bw[4][2];
            ldsm4(xx[0][0], xx[0][1], xx[0][2], xx[0][3], bX + (a_row)*PITCH2     + kb + a_coff);
            ldsm4(xx[1][0], xx[1][1], xx[1][2], xx[1][3], bX + (a_row+16)*PITCH2 + kb + a_coff);
            ldsm4(yy[0][0], yy[0][1], yy[0][2], yy[0][3], bY + (a_row)*PITCH2     + kb + a_coff);
            ldsm4(yy[1][0], yy[1][1], yy[1][2], yy[1][3], bY + (a_row+16)*PITCH2 + kb + a_coff);
#pragma unroll
            for (int p = 0; p < 2; p++) {
                int nr = wn*32 + p*16 + b_row;
                ldsm4(bw[2*p][0], bw[2*p][1], bw[2*p+1][0], bw[2*p+1][1],
                      bW + nr*PITCH2 + kb + b_coff);
            }
#pragma unroll
            for (int mi = 0; mi < 2; mi++)
#pragma unroll
                for (int ni = 0; ni < 4; ni++) {
                    mmaf16(accx[mi][ni], xx[mi], bw[ni]);
                    mmaf16(accy[mi][ni], yy[mi], bw[ni]);
                }
        }
    }

    int sec = bx / 12;
    int h   = bx - sec*12;
#pragma unroll
    for (int mi = 0; mi < 2; mi++) {
#pragma unroll
        for (int e2 = 0; e2 < 2; e2++) {
            int r = m0 + wm*32 + mi*16 + (lane >> 2) + e2*8;
            int bb = r >> 10, n = r & 1023;
            size_t obase = (((size_t)bb*NH + h)*SEQ + n)*HD;
#pragma unroll
            for (int ni = 0; ni < 4; ni++) {
                int d = wn*32 + ni*8 + 2*(lane & 3);
                float ax0 = accx[mi][ni][2*e2], ax1 = accx[mi][ni][2*e2+1];
                float ay0 = accy[mi][ni][2*e2], ay1 = accy[mi][ni][2*e2+1];
                if (sec == 0) {
                    float b0 = qb[j0 + d], b1 = qb[j0 + d + 1];
                    float o0 = (0.125f*LOG2E)*(ax0+b0)*(1.f + sigmoidf_(ay0+b0));
                    float o1 = (0.125f*LOG2E)*(ax1+b1)*(1.f + sigmoidf_(ay1+b1));
                    *(__half2*)(g_q + obase + d) = __floats2half2_rn(o0, o1);
                } else {
                    float b0 = kvb[j0 - CC + d], b1 = kvb[j0 - CC + d + 1];
                    float o0 = sigmoidf_(ay0+b0)*(ax0+b0+1.f);
                    float o1 = sigmoidf_(ay1+b1)*(ax1+b1+1.f);
                    __half* dst = (sec == 1) ? g_k : g_v;
                    *(__half2*)(dst + obase + d) = __floats2half2_rn(o0, o1);
                }
            }
        }
    }
}

// ---------------------------------------------------------------------------
// proj GEMM (unchanged).
// ---------------------------------------------------------------------------
#define BUFP  18432
#define PSTG  (2*BUFP)

__global__ __launch_bounds__(256, 2)
void hgemm_proj(const __half* __restrict__ A, const __half* __restrict__ W,
                float* __restrict__ C, const float* __restrict__ bias) {
    extern __shared__ __align__(16) char smraw[];
    uint32_t smb = smem_u32(smraw);
    int t = threadIdx.x, lane = t & 31, w = t >> 5;
    int wm = w >> 1, wn = w & 1;
    int am0 = blockIdx.y * 128, wn0 = blockIdx.x * 128;

    const __half* sa = A + (size_t)am0*CC;
    const __half* sw = W + (size_t)wn0*CC;

    auto load_stage = [&](int s, int k0) {
        uint32_t base = smb + (s & 1)*PSTG;
#pragma unroll
        for (int i = 0; i < 4; i++) {
            int c = t + i*256;
            int row = c >> 3, ch = c & 7;
            cpa16(base + row*PITCH2 + ch*16,        sa + (size_t)row*CC + k0 + ch*8);
            cpa16(base + BUFP + row*PITCH2 + ch*16, sw + (size_t)row*CC + k0 + ch*8);
        }
        cpa_commit();
    };

    float acc[2][8][4];
#pragma unroll
    for (int mi = 0; mi < 2; mi++)
#pragma unroll
        for (int ni = 0; ni < 8; ni++)
#pragma unroll
            for (int e = 0; e < 4; e++) acc[mi][ni][e] = 0.f;

    load_stage(0, 0);

    const int NSTG = CC/64;
    int a_row  = wm*32 + (lane & 15);
    int a_coff = (lane >> 4) * 16;
    int b_row  = (lane & 7) + ((lane >> 1) & 8);
    int b_coff = (lane & 8) * 2;

#pragma unroll 1
    for (int s = 0; s < NSTG; s++) {
        cpa_wait<0>();
        __syncthreads();
        if (s + 1 < NSTG) load_stage(s + 1, (s + 1)*64);
        uint32_t bA = smb + (s & 1)*PSTG;
        uint32_t bW = bA + BUFP;
#pragma unroll
        for (int ks = 0; ks < 4; ks++) {
            int kb = ks*32;
            uint32_t aa[2][4], bw[8][2];
            ldsm4(aa[0][0], aa[0][1], aa[0][2], aa[0][3], bA + (a_row)*PITCH2     + kb + a_coff);
            ldsm4(aa[1][0], aa[1][1], aa[1][2], aa[1][3], bA + (a_row+16)*PITCH2 + kb + a_coff);
#pragma unroll
            for (int p = 0; p < 4; p++) {
                int nr = wn*64 + p*16 + b_row;
                ldsm4(bw[2*p][0], bw[2*p][1], bw[2*p+1][0], bw[2*p+1][1],
                      bW + nr*PITCH2 + kb + b_coff);
            }
#pragma unroll
            for (int mi = 0; mi < 2; mi++)
#pragma unroll
                for (int ni = 0; ni < 8; ni++)
                    mmaf16(acc[mi][ni], aa[mi], bw[ni]);
        }
    }

#pragma unroll
    for (int mi = 0; mi < 2; mi++) {
        int row = am0 + wm*32 + mi*16 + (lane >> 2);
#pragma unroll
        for (int ni = 0; ni < 8; ni++) {
            int col = wn0 + wn*64 + ni*8 + 2*(lane & 3);
            float b0 = bias[col], b1 = bias[col+1];
            *(float2*)(C + (size_t)row*CC + col)     = make_float2(acc[mi][ni][0]+b0, acc[mi][ni][1]+b1);
            *(float2*)(C + (size_t)(row+8)*CC + col) = make_float2(acc[mi][ni][2]+b0, acc[mi][ni][3]+b1);
        }
    }
}

// ---------------------------------------------------------------------------
// TC flash attention with DEFERRED PV: at iter kt issue QK(kt), then
// rescale+PV(kt-1)+ones(kt-1) (fills the QK drain window), then softmax(kt).
// 4-stage ring prefetches kt+2 (stage (kt-2)&3 — disjoint from live kt, kt-1).
// ---------------------------------------------------------------------------
__global__ __launch_bounds__(256, 2)
void attn_mma() {
    extern __shared__ __align__(16) char smraw[];
    uint32_t smb = smem_u32(smraw);
    int qt = blockIdx.x, bh = blockIdx.y;
    int t = threadIdx.x, lane = t & 31, w = t >> 5;
    const __half* qp = g_q + (size_t)bh*SEQ*HD + (size_t)qt*128*HD;
    const __half* kp = g_k + (size_t)bh*SEQ*HD;
    const __half* vp = g_v + (size_t)bh*SEQ*HD;

#pragma unroll
    for (int i = 0; i < 4; i++) {
        int c = t + i*256;
        int row = c >> 3, ch = c & 7;
        cpa16(smb + swzb(row, ch*16), qp + (size_t)row*HD + ch*8);
    }
    cpa_commit();

    auto load_kv = [&](int kt) {
        uint32_t base = smb + (kt & 3)*0x4000;
#pragma unroll
        for (int i = 0; i < 2; i++) {
            int c = t + i*256;
            int row = c >> 3, ch = c & 7;
            uint32_t off = swzb(row, ch*16);
            const size_t go = (size_t)(kt*64 + row)*HD + ch*8;
            cpa16(base + 0x0000 + off, kp + go);
            cpa16(base + 0x2000 + off, vp + go);
        }
        cpa_commit();
    };

    cpa_wait<0>();
    __syncthreads();

    uint32_t qf[4][4];
    int arow = w*16 + (lane & 15);
    int acb0 = (lane >> 4) << 4;
#pragma unroll
    for (int ks = 0; ks < 4; ks++) {
        uint32_t off = swzb(arow, ks*32 + acb0);
        ldsm4(qf[ks][0], qf[ks][1], qf[ks][2], qf[ks][3], smb + off);
    }
    __syncthreads();
    load_kv(0); load_kv(1);

    float O[8][4], lacc[4];
#pragma unroll
    for (int nd = 0; nd < 8; nd++)
#pragma unroll
        for (int e = 0; e < 4; e++) O[nd][e] = 0.f;
#pragma unroll
    for (int e = 0; e < 4; e++) lacc[e] = 0.f;
    float m0 = -1e30f, m1 = -1e30f;
    float a0p = 1.f, a1p = 1.f;
    uint32_t pfp[4][4];

    const uint32_t ONES2 = 0x3C003C00u;
    uint32_t onesb[2] = { ONES2, ONES2 };

    int krow_b = (lane & 7) + ((lane >> 1) & 8);
    int kcb_b  = (lane & 8) << 1;
    int vrow_b = lane & 15;
    int vcb_b  = (lane >> 4) << 4;

#pragma unroll 1
    for (int kt = 0; kt < 16; kt++) {
        if (kt >= 15) cpa_wait<0>(); else cpa_wait<1>();
        __syncthreads();
        if (kt + 2 < 16) load_kv(kt + 2);
        uint32_t bK = smb + (kt & 3)*0x4000;

        // --- QK(kt) ---
        float sc[8][4];
#pragma unroll
        for (int jj = 0; jj < 8; jj++)
#pragma unroll
            for (int e = 0; e < 4; e++) sc[jj][e] = 0.f;
#pragma unroll
        for (int ks = 0; ks < 4; ks++) {
#pragma unroll
            for (int p = 0; p < 4; p++) {
                uint32_t k4[4];
                int krow = 16*p + krow_b;
                ldsm4(k4[0], k4[1], k4[2], k4[3], bK + swzb(krow, ks*32 + kcb_b));
                mmaf16(sc[2*p],   qf[ks], k4+0);
                mmaf16(sc[2*p+1], qf[ks], k4+2);
            }
        }

        // --- deferred: rescale + PV(kt-1) + ones(kt-1), overlaps QK drain ---
        if (kt > 0) {
#pragma unroll
            for (int nd = 0; nd < 8; nd++) {
                O[nd][0] *= a0p; O[nd][1] *= a0p;
                O[nd][2] *= a1p; O[nd][3] *= a1p;
            }
            lacc[0] *= a0p; lacc[1] *= a0p; lacc[2] *= a1p; lacc[3] *= a1p;
            uint32_t bVp = smb + ((kt - 1) & 3)*0x4000 + 0x2000;
#pragma unroll
            for (int ks2 = 0; ks2 < 4; ks2++)
                mmaf16(lacc, pfp[ks2], onesb);
#pragma unroll
            for (int ks2 = 0; ks2 < 4; ks2++) {
#pragma unroll
                for (int pp = 0; pp < 4; pp++) {
                    uint32_t v4[4];
                    int vrow = ks2*16 + vrow_b;
                    ldsm4t(v4[0], v4[1], v4[2], v4[3], bVp + swzb(vrow, pp*32 + vcb_b));
                    mmaf16(O[2*pp],   pfp[ks2], v4+0);
                    mmaf16(O[2*pp+1], pfp[ks2], v4+2);
                }
            }
        }

        // --- softmax(kt) ---
        float rm0 = -1e30f, rm1 = -1e30f;
#pragma unroll
        for (int jj = 0; jj < 8; jj++) {
            rm0 = fmaxf(rm0, fmaxf(sc[jj][0], sc[jj][1]));
            rm1 = fmaxf(rm1, fmaxf(sc[jj][2], sc[jj][3]));
        }
        rm0 = fmaxf(rm0, __shfl_xor_sync(0xffffffffu, rm0, 1));
        rm0 = fmaxf(rm0, __shfl_xor_sync(0xffffffffu, rm0, 2));
        rm1 = fmaxf(rm1, __shfl_xor_sync(0xffffffffu, rm1, 1));
        rm1 = fmaxf(rm1, __shfl_xor_sync(0xffffffffu, rm1, 2));
        float mn0 = fmaxf(m0, rm0), mn1 = fmaxf(m1, rm1);
        a0p = exp2f(m0 - mn0); a1p = exp2f(m1 - mn1);
        m0 = mn0; m1 = mn1;
#pragma unroll
        for (int jj = 0; jj < 4; jj++) {
            pfp[jj][0] = ex2h2(h2pack(sc[2*jj][0]-mn0,   sc[2*jj][1]-mn0));
            pfp[jj][1] = ex2h2(h2pack(sc[2*jj][2]-mn1,   sc[2*jj][3]-mn1));
            pfp[jj][2] = ex2h2(h2pack(sc[2*jj+1][0]-mn0, sc[2*jj+1][1]-mn0));
            pfp[jj][3] = ex2h2(h2pack(sc[2*jj+1][2]-mn1, sc[2*jj+1][3]-mn1));
        }
    }

    // --- tail: apply last rescale + PV(15) + ones(15) ---
    {
#pragma unroll
        for (int nd = 0; nd < 8; nd++) {
            O[nd][0] *= a0p; O[nd][1] *= a0p;
            O[nd][2] *= a1p; O[nd][3] *= a1p;
        }
        lacc[0] *= a0p; lacc[1] *= a0p; lacc[2] *= a1p; lacc[3] *= a1p;
        uint32_t bVp = smb + (15 & 3)*0x4000 + 0x2000;
#pragma unroll
        for (int ks2 = 0; ks2 < 4; ks2++)
            mmaf16(lacc, pfp[ks2], onesb);
#pragma unroll
        for (int ks2 = 0; ks2 < 4; ks2++) {
#pragma unroll
            for (int pp = 0; pp < 4; pp++) {
                uint32_t v4[4];
                int vrow = ks2*16 + vrow_b;
                ldsm4t(v4[0], v4[1], v4[2], v4[3], bVp + swzb(vrow, pp*32 + vcb_b));
                mmaf16(O[2*pp],   pfp[ks2], v4+0);
                mmaf16(O[2*pp+1], pfp[ks2], v4+2);
            }
        }
    }

    float inv0 = 1.f / lacc[0], inv1 = 1.f / lacc[2];
    int g = lane >> 2, t2 = (lane & 3)*2;
    int bb = bh / NH, h = bh - bb*NH;
    int n0 = qt*128 + w*16 + g;
#pragma unroll
    for (int nd = 0; nd < 8; nd++) {
        int col = h*64 + nd*8 + t2;
        size_t o0 = ((size_t)bb*SEQ + n0)*CC + col;
        size_t o1 = ((size_t)bb*SEQ + n0 + 8)*CC + col;
        *(__half2*)(g_ao + o0) = __floats2half2_rn(O[nd][0]*inv0, O[nd][1]*inv0);
        *(__half2*)(g_ao + o1) = __floats2half2_rn(O[nd][2]*inv1, O[nd][3]*inv1);
    }
}

// ---------------------------------------------------------------------------
extern "C" void kernel_launch(void* const* d_in, const int* in_sizes, int n_in,
                              void* d_out, int out_size) {
    const float* x      = (const float*)d_in[0];
    const float* y      = (const float*)d_in[1];
    const float* q_w    = (const float*)d_in[2];
    const float* q_b    = (const float*)d_in[3];
    const float* kv_w   = (const float*)d_in[4];
    const float* kv_b   = (const float*)d_in[5];
    const float* proj_w = (const float*)d_in[6];
    const float* proj_b = (const float*)d_in[7];
    const float* ln_g   = (const float*)d_in[8];
    const float* ln_b   = (const float*)d_in[9];
    float* out = (float*)d_out;

    void *pao, *pp;
    cudaGetSymbolAddress(&pao, g_ao);
    cudaGetSymbolAddress(&pp,  g_p);

    prep_all<<<1184, 256>>>(x, q_w, kv_w, proj_w);

    int smln = 32*LNP*(int)sizeof(float);
    cudaFuncSetAttribute(ln_kernel, cudaFuncAttributeMaxDynamicSharedMemorySize, smln);
    ln_kernel<<<dim3(32, 8), 256, smln>>>(y, ln_g, ln_b);

    int smq = 2*QSTG;
    cudaFuncSetAttribute(qkv_fused, cudaFuncAttributeMaxDynamicSharedMemorySize, smq);
    qkv_fused<<<dim3(36, 64), 256, smq>>>(q_b, kv_b);

    int sma = 4*0x4000;
    cudaFuncSetAttribute(attn_mma, cudaFuncAttributeMaxDynamicSharedMemorySize, sma);
    attn_mma<<<dim3(8, 96), 256, sma>>>();

    int smp = 2*PSTG;
    cudaFuncSetAttribute(hgemm_proj, cudaFuncAttributeMaxDynamicSharedMemorySize, smp);
    hgemm_proj<<<dim3(6, 64), 256, smp>>>(
        (const __half*)pao, (const __half*)pp, out, proj_b);
}